// round 3
// baseline (speedup 1.0000x reference)
#include <cuda_runtime.h>
#include <math.h>

#define BATCH 2
#define SEQ   2048
#define DIM   1024
#define FFN   4096
#define HEADS 8
#define HD    128
#define HV    128
#define VD    1024
#define NLAYERS 2
#define BL    (BATCH*SEQ)          // 4096
#define EPSV  1e-5f

// ---------------- scratch (static device globals; no allocations) ----------
__device__ float g_X  [BL*DIM];
__device__ float g_Xn [BL*DIM];
__device__ float g_Q  [BL*DIM];
__device__ float g_K  [BL*DIM];
__device__ float g_V  [BL*DIM];
__device__ float g_G  [BL*DIM];
__device__ float g_Y  [BL*DIM];
__device__ float g_Yg [BL*DIM];
__device__ float g_Att[BL*DIM];
__device__ float g_Hf [BL*FFN];
__device__ float g_Wqp[DIM*DIM];
__device__ float g_Wkp[DIM*DIM];
__device__ float g_Wvp[DIM*DIM];

// ---------------- small helpers -------------------------------------------
__device__ __forceinline__ float gelu_f(float x) {
    return 0.5f * x * (1.0f + erff(x * 0.70710678118654752f));
}

// ---------------- copy X -> scratch ---------------------------------------
__global__ void copy_k(const float* __restrict__ src, float* __restrict__ dst, int n4) {
    int i = blockIdx.x * blockDim.x + threadIdx.x;
    if (i < n4) ((float4*)dst)[i] = ((const float4*)src)[i];
}

// ---------------- pack head-major weights to [d, h*e] ----------------------
__global__ void pack_qkv_k(const float* __restrict__ Wq, const float* __restrict__ Wk,
                           const float* __restrict__ Wv,
                           float* __restrict__ Pq, float* __restrict__ Pk, float* __restrict__ Pv) {
    int idx = blockIdx.x * blockDim.x + threadIdx.x;       // over DIM*DIM
    if (idx >= DIM * DIM) return;
    int d = idx >> 10;
    int h = (idx >> 7) & 7;
    int e = idx & 127;
    int src = (h * DIM + d) * HD + e;                      // W[h][d][e]
    Pq[idx] = Wq[src];
    Pk[idx] = Wk[src];
    Pv[idx] = Wv[src];
}

// ---------------- layernorm over 1024 (one block per row) -----------------
__global__ void __launch_bounds__(256) layernorm_k(const float* __restrict__ in,
        float* __restrict__ out, const float* __restrict__ w, const float* __restrict__ bb) {
    int row = blockIdx.x, tid = threadIdx.x;
    const float4 xv = *(const float4*)(in + (size_t)row * DIM + tid * 4);
    float s  = xv.x + xv.y + xv.z + xv.w;
    float ss = xv.x*xv.x + xv.y*xv.y + xv.z*xv.z + xv.w*xv.w;
    #pragma unroll
    for (int o = 16; o; o >>= 1) {
        s  += __shfl_xor_sync(0xffffffffu, s,  o);
        ss += __shfl_xor_sync(0xffffffffu, ss, o);
    }
    __shared__ float sw[8], ssw[8], stat[2];
    int wid = tid >> 5, lane = tid & 31;
    if (!lane) { sw[wid] = s; ssw[wid] = ss; }
    __syncthreads();
    if (tid == 0) {
        float S = 0.f, SS = 0.f;
        #pragma unroll
        for (int i = 0; i < 8; i++) { S += sw[i]; SS += ssw[i]; }
        float mean = S * (1.f / DIM);
        float var  = SS * (1.f / DIM) - mean * mean;
        stat[0] = mean;
        stat[1] = rsqrtf(var + EPSV);
    }
    __syncthreads();
    float mean = stat[0], rstd = stat[1];
    const float4 wv = *(const float4*)(w  + tid * 4);
    const float4 bv = *(const float4*)(bb + tid * 4);
    float4 o;
    o.x = (xv.x - mean) * rstd * wv.x + bv.x;
    o.y = (xv.y - mean) * rstd * wv.y + bv.y;
    o.z = (xv.z - mean) * rstd * wv.z + bv.z;
    o.w = (xv.w - mean) * rstd * wv.w + bv.w;
    *(float4*)(out + (size_t)row * DIM + tid * 4) = o;
}

// ---------------- SGEMM: C[M,N] = A[M,K] @ B[K,N]  (+ epilogue) ------------
// EPI: 0 none | 1 +R | 2 +bias,gelu | 3 +bias,+R
template<int EPI>
__global__ void __launch_bounds__(256) sgemm_k(const float* __restrict__ A,
        const float* __restrict__ Bw, float* __restrict__ C,
        const float* __restrict__ bias, const float* __restrict__ R,
        int M, int N, int K) {
    __shared__ float As[8][128];
    __shared__ float Bs[8][128];
    const int tid = threadIdx.x;
    const int tx = tid & 15, ty = tid >> 4;
    const int row0 = blockIdx.y * 128, col0 = blockIdx.x * 128;
    const int ar = tid >> 1, ac = (tid & 1) * 4;     // A tile load coords
    const int br = tid >> 5, bc = (tid & 31) * 4;    // B tile load coords

    float acc[8][8];
    #pragma unroll
    for (int i = 0; i < 8; i++)
        #pragma unroll
        for (int j = 0; j < 8; j++) acc[i][j] = 0.f;

    for (int k0 = 0; k0 < K; k0 += 8) {
        float4 av = *(const float4*)&A[(size_t)(row0 + ar) * K + k0 + ac];
        float4 bv = *(const float4*)&Bw[(size_t)(k0 + br) * N + col0 + bc];
        As[ac + 0][ar] = av.x;
        As[ac + 1][ar] = av.y;
        As[ac + 2][ar] = av.z;
        As[ac + 3][ar] = av.w;
        *(float4*)&Bs[br][bc] = bv;
        __syncthreads();
        #pragma unroll
        for (int kk = 0; kk < 8; kk++) {
            float4 a0 = *(const float4*)&As[kk][ty * 8];
            float4 a1 = *(const float4*)&As[kk][ty * 8 + 4];
            float4 b0 = *(const float4*)&Bs[kk][tx * 8];
            float4 b1 = *(const float4*)&Bs[kk][tx * 8 + 4];
            float af[8] = {a0.x, a0.y, a0.z, a0.w, a1.x, a1.y, a1.z, a1.w};
            float bf[8] = {b0.x, b0.y, b0.z, b0.w, b1.x, b1.y, b1.z, b1.w};
            #pragma unroll
            for (int i = 0; i < 8; i++)
                #pragma unroll
                for (int j = 0; j < 8; j++)
                    acc[i][j] += af[i] * bf[j];
        }
        __syncthreads();
    }

    const int rbase = row0 + ty * 8, cbase = col0 + tx * 8;
    float bvv[8];
    if (EPI == 2 || EPI == 3) {
        #pragma unroll
        for (int j = 0; j < 8; j++) bvv[j] = bias[cbase + j];
    }
    #pragma unroll
    for (int i = 0; i < 8; i++) {
        size_t roff = (size_t)(rbase + i) * N + cbase;
        float v[8];
        #pragma unroll
        for (int j = 0; j < 8; j++) {
            float x = acc[i][j];
            if (EPI == 2 || EPI == 3) x += bvv[j];
            if (EPI == 2) x = gelu_f(x);
            if (EPI == 1 || EPI == 3) x += R[roff + j];
            v[j] = x;
        }
        *(float4*)&C[roff]     = make_float4(v[0], v[1], v[2], v[3]);
        *(float4*)&C[roff + 4] = make_float4(v[4], v[5], v[6], v[7]);
    }
}

// ---------------- xPos rotary (in-place on Q and K) ------------------------
__global__ void xpos_k(float* __restrict__ Q, float* __restrict__ K) {
    int idx = blockIdx.x * blockDim.x + threadIdx.x;  // over B*L*H*64 pairs
    if (idx >= BATCH * SEQ * HEADS * 64) return;
    int p = idx & 63;
    int h = (idx >> 6) & 7;
    int l = (idx >> 9) & (SEQ - 1);
    int b = idx >> (9 + 11);
    size_t base = ((size_t)(b * SEQ + l)) * DIM + h * HD + 2 * p;
    float pos = (float)l;
    float bs  = (2.f * p + 0.4f * HD) / (1.4f * HD);
    float sc  = powf(bs, pos * (1.f / 512.f));
    float invf = expf(-(float)p * (logf(10000.f) / 64.f));
    float ang = pos * invf;
    float sn, cs;
    sincosf(ang, &sn, &cs);
    float q0 = Q[base], q1 = Q[base + 1];
    Q[base]     = q0 * cs * sc - q1 * sn * sc;
    Q[base + 1] = q1 * cs * sc + q0 * sn * sc;
    float isc = 1.f / sc;
    float k0 = K[base], k1 = K[base + 1];
    K[base]     = k0 * cs * isc - k1 * sn * isc;
    K[base + 1] = k1 * cs * isc + k0 * sn * isc;
}

// ---------------- fused retention attention --------------------------------
// Y[b,h,l,v] = sum_m (Q_l . K_m) * gamma_h^(l-m) [l>=m] * V[m,v]
#define ATTN_SMEM ((3*64*132 + 64*68)*4)

__global__ void __launch_bounds__(256) attn_k(const float* __restrict__ Q,
        const float* __restrict__ K, const float* __restrict__ V, float* __restrict__ Y) {
    extern __shared__ float sm[];
    float* Qs = sm;                 // [64][132]
    float* Ks = sm + 64 * 132;      // [64][132]
    float* Vs = sm + 2 * 64 * 132;  // [64][132]
    float* Ss = sm + 3 * 64 * 132;  // [64][68]
    const int tid = threadIdx.x;
    const int q0  = blockIdx.x * 64;
    const int bh  = blockIdx.y;
    const int b = bh >> 3, h = bh & 7;
    const float gamma = 1.f - expf(-3.4657359028f + (float)h * -0.3960840962f);
    const float lg = logf(gamma);

    for (int i = tid; i < 64 * 32; i += 256) {
        int r = i >> 5, c = (i & 31) << 2;
        *(float4*)&Qs[r * 132 + c] =
            *(const float4*)&Q[((size_t)(b * SEQ + q0 + r)) * DIM + h * HD + c];
    }

    float acc[8][4];
    #pragma unroll
    for (int i = 0; i < 8; i++) { acc[i][0]=acc[i][1]=acc[i][2]=acc[i][3]=0.f; }
    const int yr = (tid >> 5) << 3;
    const int yc = (tid & 31) << 2;
    const int si = (tid >> 4) << 2;
    const int sj = (tid & 15) << 2;

    const int nmt = (q0 >> 6) + 1;
    for (int mt = 0; mt < nmt; mt++) {
        const int m0 = mt << 6;
        __syncthreads();
        for (int i = tid; i < 64 * 32; i += 256) {
            int r = i >> 5, c = (i & 31) << 2;
            size_t src = ((size_t)(b * SEQ + m0 + r)) * DIM + h * HD + c;
            *(float4*)&Ks[r * 132 + c] = *(const float4*)&K[src];
            *(float4*)&Vs[r * 132 + c] = *(const float4*)&V[src];
        }
        __syncthreads();
        float s[4][4];
        #pragma unroll
        for (int i = 0; i < 4; i++)
            #pragma unroll
            for (int j = 0; j < 4; j++) s[i][j] = 0.f;
        #pragma unroll 4
        for (int e = 0; e < 128; e += 4) {
            float4 qv[4], kv[4];
            #pragma unroll
            for (int i = 0; i < 4; i++) qv[i] = *(const float4*)&Qs[(si + i) * 132 + e];
            #pragma unroll
            for (int j = 0; j < 4; j++) kv[j] = *(const float4*)&Ks[(sj + j) * 132 + e];
            #pragma unroll
            for (int i = 0; i < 4; i++)
                #pragma unroll
                for (int j = 0; j < 4; j++)
                    s[i][j] += qv[i].x * kv[j].x + qv[i].y * kv[j].y
                             + qv[i].z * kv[j].z + qv[i].w * kv[j].w;
        }
        #pragma unroll
        for (int i = 0; i < 4; i++)
            #pragma unroll
            for (int j = 0; j < 4; j++) {
                int li = q0 + si + i, mj = m0 + sj + j;
                float d = (li >= mj) ? __expf(lg * (float)(li - mj)) : 0.f;
                Ss[(si + i) * 68 + sj + j] = s[i][j] * d;
            }
        __syncthreads();
        #pragma unroll 4
        for (int j = 0; j < 64; j++) {
            float4 vv = *(const float4*)&Vs[j * 132 + yc];
            #pragma unroll
            for (int i = 0; i < 8; i++) {
                float sv = Ss[(yr + i) * 68 + j];
                acc[i][0] += sv * vv.x;
                acc[i][1] += sv * vv.y;
                acc[i][2] += sv * vv.z;
                acc[i][3] += sv * vv.w;
            }
        }
    }
    #pragma unroll
    for (int i = 0; i < 8; i++) {
        *(float4*)&Y[((size_t)((b * 8 + h) * SEQ) + q0 + yr + i) * HV + yc] =
            make_float4(acc[i][0], acc[i][1], acc[i][2], acc[i][3]);
    }
}

// ---------------- per-head groupnorm + SiLU gate, rearrange to [b,l,h*v] ---
__global__ void __launch_bounds__(256) gn_gate_k(const float* __restrict__ Y,
        const float* __restrict__ G, const float* __restrict__ gnw,
        const float* __restrict__ gnb, float* __restrict__ out) {
    int gwarp = (blockIdx.x * blockDim.x + threadIdx.x) >> 5;   // row over B*H*L
    int lane = threadIdx.x & 31;
    if (gwarp >= BATCH * HEADS * SEQ) return;
    int b = gwarp / (HEADS * SEQ);
    int h = (gwarp / SEQ) & 7;
    int l = gwarp & (SEQ - 1);
    const float* y = Y + (size_t)gwarp * HV;
    float v0 = y[lane], v1 = y[lane + 32], v2 = y[lane + 64], v3 = y[lane + 96];
    float s  = v0 + v1 + v2 + v3;
    float ss = v0*v0 + v1*v1 + v2*v2 + v3*v3;
    #pragma unroll
    for (int o = 16; o; o >>= 1) {
        s  += __shfl_xor_sync(0xffffffffu, s,  o);
        ss += __shfl_xor_sync(0xffffffffu, ss, o);
    }
    float mean = s * (1.f / HV);
    float var  = ss * (1.f / HV) - mean * mean;
    float rstd = rsqrtf(var + EPSV);
    size_t ob = ((size_t)(b * SEQ + l)) * VD + h * HV;
    float vv[4] = {v0, v1, v2, v3};
    #pragma unroll
    for (int i = 0; i < 4; i++) {
        int c = lane + i * 32;
        float g = G[ob + c];
        float gate = g / (1.f + expf(-g));
        out[ob + c] = ((vv[i] - mean) * rstd * gnw[h * HV + c] + gnb[h * HV + c]) * gate;
    }
}

// ---------------- host launcher --------------------------------------------
extern "C" void kernel_launch(void* const* d_in, const int* in_sizes, int n_in,
                              void* d_out, int out_size) {
    const float* X    = (const float*)d_in[0];
    const float* Wq   = (const float*)d_in[1];
    const float* Wk   = (const float*)d_in[2];
    const float* Wv   = (const float*)d_in[3];
    const float* W_G  = (const float*)d_in[4];
    const float* W_O  = (const float*)d_in[5];
    const float* gnw  = (const float*)d_in[6];
    const float* gnb  = (const float*)d_in[7];
    const float* ln1w = (const float*)d_in[8];
    const float* ln1b = (const float*)d_in[9];
    const float* ln2w = (const float*)d_in[10];
    const float* ln2b = (const float*)d_in[11];
    const float* fw1  = (const float*)d_in[12];
    const float* fb1  = (const float*)d_in[13];
    const float* fw2  = (const float*)d_in[14];
    const float* fb2  = (const float*)d_in[15];
    float* out = (float*)d_out;

    void* p;
    cudaGetSymbolAddress(&p, g_X);   float* pX   = (float*)p;
    cudaGetSymbolAddress(&p, g_Xn);  float* pXn  = (float*)p;
    cudaGetSymbolAddress(&p, g_Q);   float* pQ   = (float*)p;
    cudaGetSymbolAddress(&p, g_K);   float* pK   = (float*)p;
    cudaGetSymbolAddress(&p, g_V);   float* pV   = (float*)p;
    cudaGetSymbolAddress(&p, g_G);   float* pG   = (float*)p;
    cudaGetSymbolAddress(&p, g_Y);   float* pY   = (float*)p;
    cudaGetSymbolAddress(&p, g_Yg);  float* pYg  = (float*)p;
    cudaGetSymbolAddress(&p, g_Att); float* pAtt = (float*)p;
    cudaGetSymbolAddress(&p, g_Hf);  float* pH   = (float*)p;
    cudaGetSymbolAddress(&p, g_Wqp); float* pWq  = (float*)p;
    cudaGetSymbolAddress(&p, g_Wkp); float* pWk  = (float*)p;
    cudaGetSymbolAddress(&p, g_Wvp); float* pWv  = (float*)p;

    cudaFuncSetAttribute(attn_k, cudaFuncAttributeMaxDynamicSharedMemorySize, ATTN_SMEM);

    copy_k<<<(BL * DIM / 4 + 255) / 256, 256>>>(X, pX, BL * DIM / 4);

    dim3 g8(DIM / 128, BL / 128);
    dim3 gf1(FFN / 128, BL / 128);

    for (int i = 0; i < NLAYERS; i++) {
        size_t wofs = (size_t)i * HEADS * DIM * HD;
        pack_qkv_k<<<(DIM * DIM + 255) / 256, 256>>>(Wq + wofs, Wk + wofs, Wv + wofs,
                                                     pWq, pWk, pWv);
        layernorm_k<<<BL, 256>>>(pX, pXn, ln1w + i * DIM, ln1b + i * DIM);

        sgemm_k<0><<<g8, 256>>>(pXn, pWq, pQ, nullptr, nullptr, BL, DIM, DIM);
        sgemm_k<0><<<g8, 256>>>(pXn, pWk, pK, nullptr, nullptr, BL, DIM, DIM);
        sgemm_k<0><<<g8, 256>>>(pXn, pWv, pV, nullptr, nullptr, BL, DIM, DIM);
        sgemm_k<0><<<g8, 256>>>(pXn, W_G + (size_t)i * DIM * VD, pG, nullptr, nullptr,
                                BL, DIM, DIM);

        xpos_k<<<(BATCH * SEQ * HEADS * 64 + 255) / 256, 256>>>(pQ, pK);

        attn_k<<<dim3(SEQ / 64, BATCH * HEADS), 256, ATTN_SMEM>>>(pQ, pK, pV, pY);

        gn_gate_k<<<(BATCH * HEADS * SEQ) / 8, 256>>>(pY, pG, gnw + i * VD, gnb + i * VD, pYg);

        sgemm_k<1><<<g8, 256>>>(pYg, W_O + (size_t)i * VD * DIM, pAtt, nullptr, pX,
                                BL, DIM, DIM);

        layernorm_k<<<BL, 256>>>(pAtt, pXn, ln2w + i * DIM, ln2b + i * DIM);

        sgemm_k<2><<<gf1, 256>>>(pXn, fw1 + (size_t)i * DIM * FFN, pH,
                                 fb1 + i * FFN, nullptr, BL, FFN, DIM);

        float* dst = (i == NLAYERS - 1) ? out : pX;
        sgemm_k<3><<<g8, 256>>>(pH, fw2 + (size_t)i * FFN * DIM, dst,
                                fb2 + i * DIM, pAtt, BL, DIM, FFN);
    }
}